// round 3
// baseline (speedup 1.0000x reference)
#include <cuda_runtime.h>
#include <cuda_bf16.h>
#include <cstdint>

// Problem constants (fixed by the dataset)
#define WRANKS 8
#define MDIM   4096
#define NDIM   4096
#define KDIM   1792

#define BM 128
#define BN 128
#define BK 32
#define NTHREADS 256

// smem row stride in 32-bit words; 36 => bank = (4*row + k) % 32, conflict-free
// for all fragment load patterns used below.
#define SSTRIDE 36

__device__ __forceinline__ unsigned f2tf32(float x) {
    unsigned r;
    asm("cvt.rna.tf32.f32 %0, %1;" : "=r"(r) : "f"(x));
    return r;
}

__device__ __forceinline__ void mma_tf32_m16n8k8(float c[4], const unsigned a[4], const unsigned b[2]) {
    asm volatile(
        "mma.sync.aligned.m16n8k8.row.col.f32.tf32.tf32.f32 "
        "{%0,%1,%2,%3}, {%4,%5,%6,%7}, {%8,%9}, {%0,%1,%2,%3};\n"
        : "+f"(c[0]), "+f"(c[1]), "+f"(c[2]), "+f"(c[3])
        : "r"(a[0]), "r"(a[1]), "r"(a[2]), "r"(a[3]),
          "r"(b[0]), "r"(b[1]));
}

__global__ void __launch_bounds__(NTHREADS)
gemm_ar_tf32_kernel(const float* __restrict__ input,   // [W, M, K]
                    const float* __restrict__ weight,  // [W, N, K]
                    float* __restrict__ out)           // [M, N]
{
    __shared__ unsigned As[BM * SSTRIDE];
    __shared__ unsigned Bs[BN * SSTRIDE];

    const int tid  = threadIdx.x;
    const int warp = tid >> 5;
    const int lane = tid & 31;
    const int g    = lane >> 2;   // group id (0..7)
    const int t    = lane & 3;    // thread-in-group (0..3)

    // Grid swizzle: 8-wide N-tile groups, sweep all M tiles within a group
    // so B group working set (~59MB) stays L2 resident.
    const int GW = 8;
    const int MT = MDIM / BM;  // 32
    int gid   = blockIdx.x;
    int group = gid / (GW * MT);
    int rem   = gid % (GW * MT);
    int mt    = rem / GW;
    int nt    = group * GW + (rem % GW);
    const int m0 = mt * BM;
    const int n0 = nt * BN;

    // warp tiling: 4x2 warps, each warp computes 32(M) x 64(N)
    const int wm = warp & 3;   // 0..3
    const int wn = warp >> 2;  // 0..1

    float acc[2][8][4];
    #pragma unroll
    for (int im = 0; im < 2; im++)
        #pragma unroll
        for (int in = 0; in < 8; in++)
            #pragma unroll
            for (int j = 0; j < 4; j++)
                acc[im][in][j] = 0.0f;

    // Per-thread global load coordinates: 4 float4 per array per BK tile.
    // idx = tid + i*256 -> row = idx/8 (0..127), kq = idx%8 (float4 slot)
    for (int r = 0; r < WRANKS; r++) {
        const float* Abase = input  + ((size_t)r * MDIM + m0) * KDIM;
        const float* Bbase = weight + ((size_t)r * NDIM + n0) * KDIM;
        for (int kk = 0; kk < KDIM; kk += BK) {
            // ---- load tile (global fp32 -> smem tf32) ----
            #pragma unroll
            for (int i = 0; i < 4; i++) {
                int idx = tid + i * NTHREADS;
                int row = idx >> 3;
                int kq  = idx & 7;
                const float4 av = *(const float4*)(Abase + (size_t)row * KDIM + kk + kq * 4);
                unsigned* sa = &As[row * SSTRIDE + kq * 4];
                sa[0] = f2tf32(av.x); sa[1] = f2tf32(av.y);
                sa[2] = f2tf32(av.z); sa[3] = f2tf32(av.w);
                const float4 bv = *(const float4*)(Bbase + (size_t)row * KDIM + kk + kq * 4);
                unsigned* sb = &Bs[row * SSTRIDE + kq * 4];
                sb[0] = f2tf32(bv.x); sb[1] = f2tf32(bv.y);
                sb[2] = f2tf32(bv.z); sb[3] = f2tf32(bv.w);
            }
            __syncthreads();

            // ---- compute: 4 k8 steps ----
            #pragma unroll
            for (int ks = 0; ks < 4; ks++) {
                unsigned afrag[2][4];
                unsigned bfrag[8][2];
                #pragma unroll
                for (int im = 0; im < 2; im++) {
                    int r0 = wm * 32 + im * 16 + g;
                    afrag[im][0] = As[r0 * SSTRIDE + ks * 8 + t];
                    afrag[im][1] = As[(r0 + 8) * SSTRIDE + ks * 8 + t];
                    afrag[im][2] = As[r0 * SSTRIDE + ks * 8 + t + 4];
                    afrag[im][3] = As[(r0 + 8) * SSTRIDE + ks * 8 + t + 4];
                }
                #pragma unroll
                for (int in = 0; in < 8; in++) {
                    int c0 = wn * 64 + in * 8 + g;
                    bfrag[in][0] = Bs[c0 * SSTRIDE + ks * 8 + t];
                    bfrag[in][1] = Bs[c0 * SSTRIDE + ks * 8 + t + 4];
                }
                #pragma unroll
                for (int im = 0; im < 2; im++)
                    #pragma unroll
                    for (int in = 0; in < 8; in++)
                        mma_tf32_m16n8k8(acc[im][in], afrag[im], bfrag[in]);
            }
            __syncthreads();
        }
    }

    // ---- epilogue ----
    const int m_base = m0 + wm * 32;
    const int n_base = n0 + wn * 64;
    #pragma unroll
    for (int im = 0; im < 2; im++) {
        #pragma unroll
        for (int in = 0; in < 8; in++) {
            int rr = m_base + im * 16 + g;
            int cc = n_base + in * 8 + t * 2;
            *(float2*)(out + (size_t)rr * NDIM + cc) =
                make_float2(acc[im][in][0], acc[im][in][1]);
            *(float2*)(out + (size_t)(rr + 8) * NDIM + cc) =
                make_float2(acc[im][in][2], acc[im][in][3]);
        }
    }
}

extern "C" void kernel_launch(void* const* d_in, const int* in_sizes, int n_in,
                              void* d_out, int out_size) {
    const float* input  = (const float*)d_in[0];
    const float* weight = (const float*)d_in[1];
    float* out = (float*)d_out;

    const int grid = (MDIM / BM) * (NDIM / BN);  // 1024
    gemm_ar_tf32_kernel<<<grid, NTHREADS>>>(input, weight, out);
}

// round 6
// speedup vs baseline: 1.6967x; 1.6967x over previous
#include <cuda_runtime.h>
#include <cstdint>

// ---------------- problem constants ----------------
#define WRANKS 8
#define MDIM   4096
#define NDIM   4096
#define KDIM   1792

// ---------------- tile config ----------------
#define BM 128
#define BN 128
#define BK 32
#define NTHREADS 256
#define STAGES 3
#define TOTAL_STAGES ((WRANKS * KDIM) / BK)   // 448
#define STAGES_PER_RANK (KDIM / BK)           // 56

// smem row stride in 32-bit words; 36 => bank = (4*row + k) % 32, conflict-free
// for the fragment load patterns below, and 144B row pitch keeps 16B chunks aligned.
#define SSTRIDE 36
#define TILE_WORDS (BM * SSTRIDE)             // 4608 words per operand tile
#define STAGE_WORDS (2 * TILE_WORDS)          // A + B
#define DYN_SMEM (STAGES * STAGE_WORDS * 4)   // 110592 bytes

// ---------------- tf32 scratch (pre-rounded operands) ----------------
__device__ __align__(16) unsigned g_a_tf32[WRANKS * MDIM * KDIM];
__device__ __align__(16) unsigned g_b_tf32[WRANKS * NDIM * KDIM];

// ---------------- helpers ----------------
__device__ __forceinline__ unsigned f2tf32(float x) {
    unsigned r;
    asm("cvt.rna.tf32.f32 %0, %1;" : "=r"(r) : "f"(x));
    return r;
}

__device__ __forceinline__ uint32_t smem_to_u32(const void* p) {
    uint32_t a;
    asm("{ .reg .u64 t; cvta.to.shared.u64 t, %1; cvt.u32.u64 %0, t; }" : "=r"(a) : "l"(p));
    return a;
}

__device__ __forceinline__ void cp_async16(uint32_t dst, const void* src) {
    asm volatile("cp.async.cg.shared.global [%0], [%1], 16;" :: "r"(dst), "l"(src));
}
#define CP_COMMIT() asm volatile("cp.async.commit_group;" ::: "memory")
#define CP_WAIT(n)  asm volatile("cp.async.wait_group %0;" :: "n"(n) : "memory")

__device__ __forceinline__ void mma_tf32_m16n8k8(float c[4], const unsigned a[4], const unsigned b[2]) {
    asm volatile(
        "mma.sync.aligned.m16n8k8.row.col.f32.tf32.tf32.f32 "
        "{%0,%1,%2,%3}, {%4,%5,%6,%7}, {%8,%9}, {%0,%1,%2,%3};\n"
        : "+f"(c[0]), "+f"(c[1]), "+f"(c[2]), "+f"(c[3])
        : "r"(a[0]), "r"(a[1]), "r"(a[2]), "r"(a[3]),
          "r"(b[0]), "r"(b[1]));
}

// ---------------- pass 1: fp32 -> tf32(RNA) bits ----------------
__global__ void __launch_bounds__(256) convert_tf32_kernel(
    const float4* __restrict__ a, const float4* __restrict__ b,
    uint4* __restrict__ oa, uint4* __restrict__ ob)
{
    const size_t n4 = (size_t)WRANKS * MDIM * KDIM / 4;
    size_t stride = (size_t)gridDim.x * blockDim.x;
    for (size_t i = (size_t)blockIdx.x * blockDim.x + threadIdx.x; i < n4; i += stride) {
        float4 va = a[i];
        uint4 ua = { f2tf32(va.x), f2tf32(va.y), f2tf32(va.z), f2tf32(va.w) };
        oa[i] = ua;
        float4 vb = b[i];
        uint4 ub = { f2tf32(vb.x), f2tf32(vb.y), f2tf32(vb.z), f2tf32(vb.w) };
        ob[i] = ub;
    }
}

// ---------------- pass 2: pipelined tf32 mma.sync GEMM + fused all-reduce ----------------
extern __shared__ unsigned dsm[];

__global__ void __launch_bounds__(NTHREADS, 2)
gemm_ar_tf32_pipe(const unsigned* __restrict__ ga,   // [W, M, K] tf32 bits
                  const unsigned* __restrict__ gb,   // [W, N, K] tf32 bits
                  float* __restrict__ out)           // [M, N]
{
    const int tid  = threadIdx.x;
    const int warp = tid >> 5;
    const int lane = tid & 31;
    const int g    = lane >> 2;   // 0..7
    const int t    = lane & 3;    // 0..3

    // grid swizzle: 8-wide N-tile groups so B stays L2 resident across the M sweep
    const int GW = 8;
    const int MT = MDIM / BM;  // 32
    int gid   = blockIdx.x;
    int group = gid / (GW * MT);
    int rem   = gid % (GW * MT);
    int mt    = rem / GW;
    int nt    = group * GW + (rem % GW);
    const int m0 = mt * BM;
    const int n0 = nt * BN;

    // warp tiling: 4x2 warps, each 32(M) x 64(N)
    const int wm = warp & 3;
    const int wn = warp >> 2;

    // per-thread staging coords: idx = tid + i*256 -> row = idx/8, chunk = idx%8
    const int row0  = tid >> 3;          // rows row0, row0+32, +64, +96
    const int chunk = tid & 7;           // 16B chunk within the 32-float row

    const uint32_t smem_u = smem_to_u32(dsm);

    float acc[2][8][4];
    #pragma unroll
    for (int im = 0; im < 2; im++)
        #pragma unroll
        for (int in = 0; in < 8; in++)
            #pragma unroll
            for (int j = 0; j < 4; j++)
                acc[im][in][j] = 0.0f;

    // ---- stage issue: cp.async the (rank, kk) tile into buffer buf ----
    auto issue = [&](int s, int buf) {
        const int r  = s / STAGES_PER_RANK;
        const int kk = (s % STAGES_PER_RANK) * BK;
        const unsigned* Ab = ga + ((size_t)r * MDIM + m0) * KDIM + kk + chunk * 4;
        const unsigned* Bb = gb + ((size_t)r * NDIM + n0) * KDIM + kk + chunk * 4;
        const uint32_t abase = smem_u + (buf * STAGE_WORDS) * 4;
        const uint32_t bbase = abase + TILE_WORDS * 4;
        #pragma unroll
        for (int i = 0; i < 4; i++) {
            const int row = row0 + i * 32;
            cp_async16(abase + (row * SSTRIDE + chunk * 4) * 4, Ab + (size_t)row * KDIM);
            cp_async16(bbase + (row * SSTRIDE + chunk * 4) * 4, Bb + (size_t)row * KDIM);
        }
        CP_COMMIT();
    };

    // ---- prologue: fill STAGES-1 buffers ----
    #pragma unroll
    for (int s = 0; s < STAGES - 1; s++) issue(s, s);

    int buf = 0;
    for (int s = 0; s < TOTAL_STAGES; s++) {
        CP_WAIT(STAGES - 2);       // stage s resident
        __syncthreads();

        // refill the buffer freed last iteration (safe: post-sync)
        if (s + STAGES - 1 < TOTAL_STAGES)
            issue(s + STAGES - 1, (buf + STAGES - 1) % STAGES);
        else
            CP_COMMIT();           // keep group accounting aligned

        const unsigned* As = dsm + buf * STAGE_WORDS;
        const unsigned* Bs = As + TILE_WORDS;

        #pragma unroll
        for (int ks = 0; ks < 4; ks++) {
            unsigned afrag[2][4];
            unsigned bfrag[8][2];
            #pragma unroll
            for (int im = 0; im < 2; im++) {
                int r0 = wm * 32 + im * 16 + g;
                afrag[im][0] = As[r0 * SSTRIDE + ks * 8 + t];
                afrag[im][1] = As[(r0 + 8) * SSTRIDE + ks * 8 + t];
                afrag[im][2] = As[r0 * SSTRIDE + ks * 8 + t + 4];
                afrag[im][3] = As[(r0 + 8) * SSTRIDE + ks * 8 + t + 4];
            }
            #pragma unroll
            for (int in = 0; in < 8; in++) {
                int c0 = wn * 64 + in * 8 + g;
                bfrag[in][0] = Bs[c0 * SSTRIDE + ks * 8 + t];
                bfrag[in][1] = Bs[c0 * SSTRIDE + ks * 8 + t + 4];
            }
            #pragma unroll
            for (int im = 0; im < 2; im++)
                #pragma unroll
                for (int in = 0; in < 8; in++)
                    mma_tf32_m16n8k8(acc[im][in], afrag[im], bfrag[in]);
        }

        __syncthreads();           // all reads of buf done before its next refill
        if (++buf == STAGES) buf = 0;
    }

    // ---- epilogue ----
    const int m_base = m0 + wm * 32;
    const int n_base = n0 + wn * 64;
    #pragma unroll
    for (int im = 0; im < 2; im++) {
        #pragma unroll
        for (int in = 0; in < 8; in++) {
            int rr = m_base + im * 16 + g;
            int cc = n_base + in * 8 + t * 2;
            *(float2*)(out + (size_t)rr * NDIM + cc) =
                make_float2(acc[im][in][0], acc[im][in][1]);
            *(float2*)(out + (size_t)(rr + 8) * NDIM + cc) =
                make_float2(acc[im][in][2], acc[im][in][3]);
        }
    }
}

// ---------------- host launch ----------------
extern "C" void kernel_launch(void* const* d_in, const int* in_sizes, int n_in,
                              void* d_out, int out_size) {
    const float* a = (const float*)d_in[0];
    const float* b = (const float*)d_in[1];
    float* out = (float*)d_out;

    void *pa = nullptr, *pb = nullptr;
    cudaGetSymbolAddress(&pa, g_a_tf32);
    cudaGetSymbolAddress(&pb, g_b_tf32);

    // pass 1: round both operands to tf32 (RNA) so the MMA's internal
    // truncation is exact (no coherent bias).
    convert_tf32_kernel<<<2048, 256>>>((const float4*)a, (const float4*)b,
                                       (uint4*)pa, (uint4*)pb);

    // pass 2: pipelined GEMM with the rank all-reduce fused into the K loop.
    cudaFuncSetAttribute(gemm_ar_tf32_pipe,
                         cudaFuncAttributeMaxDynamicSharedMemorySize, DYN_SMEM);
    const int grid = (MDIM / BM) * (NDIM / BN);   // 1024
    gemm_ar_tf32_pipe<<<grid, NTHREADS, DYN_SMEM>>>(
        (const unsigned*)pa, (const unsigned*)pb, out);
}